// round 10
// baseline (speedup 1.0000x reference)
#include <cuda_runtime.h>
#include <cuda_bf16.h>
#include <cstddef>
#include <cstdint>

#define S_LEN   2048
#define BATCH   32
#define IN_DIM  64
#define EMB_DIM 32
#define HID     256
#define XE      96
#define G4      1024
#define NGRP    16      // batch groups = clusters
#define CSIZE   8       // CTAs per cluster
#define TX_BYTES 2048   // per-step tx into each CTA's mbar: 8 src * 64 floats * 4B

typedef unsigned long long ull;

// ---- device scratch (module global: the sanctioned scratch mechanism) ----
__device__ float g_zx[(size_t)S_LEN * BATCH * G4];   // [t][b][row], 256 MiB

namespace {
struct EagerLoad {  // force module load before harness mem checkpoints
    EagerLoad() { void* p = nullptr; (void)cudaGetSymbolAddress(&p, g_zx); }
};
static EagerLoad eager_;
}

// ---- fast accurate activations --------------------------------------------
__device__ __forceinline__ float sigf(float x) {
    return __fdividef(1.f, 1.f + __expf(-x));
}
__device__ __forceinline__ float tanh_f(float x) {
    float ax = fabsf(x);
    float e  = __expf(-2.f * ax);            // in (0,1], never overflows
    return copysignf(__fdividef(1.f - e, 1.f + e), x);
}

// ---- f32x2 packed FMA (sm_10x; ptxas never auto-fuses this) ---------------
#define FMA2(d, a, b) \
    asm("fma.rn.f32x2 %0, %1, %2, %0;" : "+l"(d) : "l"(a), "l"(b))

__device__ __forceinline__ float hsum2(ull v) {
    float lo, hi;
    asm("mov.b64 {%0,%1}, %2;" : "=f"(lo), "=f"(hi) : "l"(v));
    return lo + hi;
}

__device__ __forceinline__ uint32_t smem_u32(const void* p) {
    uint32_t a;
    asm("{ .reg .u64 t; cvta.to.shared.u64 t, %1; cvt.u32.u64 %0, t; }"
        : "=r"(a) : "l"(p));
    return a;
}
__device__ __forceinline__ uint32_t mapa_u32(uint32_t laddr, uint32_t rank) {
    uint32_t ra;
    asm("mapa.shared::cluster.u32 %0, %1, %2;" : "=r"(ra) : "r"(laddr), "r"(rank));
    return ra;
}
// remote smem store + remote mbarrier tx-complete, hardware-ordered, async
__device__ __forceinline__ void st_async_f32(uint32_t raddr, uint32_t rmbar, float v) {
    asm volatile(
        "st.async.weak.shared::cluster.mbarrier::complete_tx::bytes.f32 [%0], %1, [%2];"
        :: "r"(raddr), "f"(v), "r"(rmbar) : "memory");
}
__device__ __forceinline__ void mbar_expect_tx(uint32_t mbar, uint32_t tx) {
    asm volatile("mbarrier.arrive.expect_tx.shared.b64 _, [%0], %1;"
                 :: "r"(mbar), "r"(tx) : "memory");
}
__device__ __forceinline__ void mbar_wait(uint32_t mbar, uint32_t parity) {
    asm volatile(
        "{\n\t.reg .pred P;\n"
        "WL_%=:\n\t"
        "mbarrier.try_wait.parity.acquire.cluster.shared::cta.b64 P, [%0], %1, 0x989680;\n\t"
        "@!P bra WL_%=;\n\t}"
        :: "r"(mbar), "r"(parity) : "memory");
}

// ---------------------------------------------------------------------------
// Kernel A: zx[t][b][row] = bias[row] + sum_i [x|emb][b][t][i] * W_ih[row][i]
// grid (16 row-tiles, 2048 t), 256 threads, FFMA2.
// ---------------------------------------------------------------------------
__global__ void __launch_bounds__(256) zx_kernel(
    const float* __restrict__ x, const float* __restrict__ emb,
    const float* __restrict__ W_ih, const float* __restrict__ bias)
{
    const int t = blockIdx.y, rbase = blockIdx.x * 64, tid = threadIdx.x;

    __shared__ __align__(16) float xe_s[BATCH][100];
    __shared__ __align__(16) float W_s[64][100];

    for (int idx = tid; idx < BATCH * IN_DIM; idx += 256) {
        int b = idx >> 6, i = idx & 63;
        xe_s[b][i] = x[((size_t)b * S_LEN + t) * IN_DIM + i];
    }
    for (int idx = tid; idx < BATCH * EMB_DIM; idx += 256) {
        int b = idx >> 5, i = idx & 31;
        xe_s[b][IN_DIM + i] = emb[((size_t)b * S_LEN + t) * EMB_DIM + i];
    }
    for (int idx = tid; idx < 64 * XE; idx += 256) {
        int r = idx / XE, i = idx - r * XE;
        W_s[r][i] = W_ih[(size_t)(rbase + r) * XE + i];
    }
    __syncthreads();

    const int m = tid & 15, b0 = (tid >> 4) * 2;

    ull acc[4][2][2];
#pragma unroll
    for (int j = 0; j < 4; ++j)
#pragma unroll
        for (int b = 0; b < 2; ++b)
            acc[j][b][0] = acc[j][b][1] = 0ull;

    const ulonglong2* xv0 = reinterpret_cast<const ulonglong2*>(&xe_s[b0][0]);
    const ulonglong2* xv1 = reinterpret_cast<const ulonglong2*>(&xe_s[b0 + 1][0]);
#pragma unroll
    for (int k4 = 0; k4 < XE / 4; ++k4) {
        ulonglong2 xa = xv0[k4], xb = xv1[k4];
#pragma unroll
        for (int j = 0; j < 4; ++j) {
            ulonglong2 w = reinterpret_cast<const ulonglong2*>(&W_s[m + 16 * j][0])[k4];
            FMA2(acc[j][0][0], w.x, xa.x);
            FMA2(acc[j][0][1], w.y, xa.y);
            FMA2(acc[j][1][0], w.x, xb.x);
            FMA2(acc[j][1][1], w.y, xb.y);
        }
    }
#pragma unroll
    for (int j = 0; j < 4; ++j) {
        int row = rbase + m + 16 * j;
        float bv = __ldg(&bias[row]);
        size_t base = ((size_t)t * BATCH + b0) * G4 + row;
        g_zx[base]      = hsum2(acc[j][0][0]) + hsum2(acc[j][0][1]) + bv;
        g_zx[base + G4] = hsum2(acc[j][1][0]) + hsum2(acc[j][1][1]) + bv;
    }
}

// ---------------------------------------------------------------------------
// Kernel B: persistent LSTM. 16 independent 8-CTA clusters (2 batches each).
// Thread (u = tid>>3, g = (tid>>1)&3, kh = tid&1): gate-row g of unit u0+u,
// k-granules (float4) G ≡ kh (mod 2), both batches. Group of 8 lanes per unit
// reduces via shfl (no smem, no __syncthreads in the loop). h exchanged via
// st.async (2 sends/lane, precomputed remote addrs) + mbarrier tx counting.
// ---------------------------------------------------------------------------
__global__ void __launch_bounds__(256, 1) __cluster_dims__(CSIZE, 1, 1)
lstm_kernel(const float* __restrict__ W_hh, float* __restrict__ out)
{
    __shared__ __align__(16) float hbuf[2][2][HID];       // [buf][b][k]
    __shared__ __align__(8)  ull   mbar[2];

    const int tid = threadIdx.x;
    const int grp = blockIdx.x / CSIZE;
    uint32_t rank;
    asm("mov.u32 %0, %%cluster_ctarank;" : "=r"(rank));
    const int b0 = grp * 2;
    const int u0 = (int)rank * 32;

    const uint32_t mbar_u32[2] = { smem_u32(&mbar[0]), smem_u32(&mbar[1]) };
    if (tid == 0) {
        asm volatile("mbarrier.init.shared.b64 [%0], 1;" :: "r"(mbar_u32[0]) : "memory");
        asm volatile("mbarrier.init.shared.b64 [%0], 1;" :: "r"(mbar_u32[1]) : "memory");
    }
    __syncthreads();
    // all mbarriers must be initialized before any peer's st.async can land
    asm volatile("barrier.cluster.arrive.aligned;" ::: "memory");
    asm volatile("barrier.cluster.wait.aligned;"   ::: "memory");

    const int u  = tid >> 3;          // unit within CTA slice (0..31)
    const int l  = tid & 7;           // lane in group
    const int g  = l >> 1;            // gate 0..3
    const int kh = l & 1;             // k-half (interleaved granules)
    const int row = g * HID + u0 + u; // global gate-row

    // ---- W slice in registers: granules G = 2j+kh, j = 0..31 (128 regs) ----
    ull Wr[64];
    {
        const ulonglong2* wrow = reinterpret_cast<const ulonglong2*>(
            W_hh + (size_t)row * HID);
#pragma unroll
        for (int j = 0; j < 32; ++j) {
            ulonglong2 w = wrow[2 * j + kh];
            Wr[2 * j]     = w.x;
            Wr[2 * j + 1] = w.y;
        }
    }

    // ---- precomputed st.async destinations: lane sends h_{b=l&1} of unit u
    //      to ranks g and g+4 (8 lanes x 2 sends cover all 8 ranks x 2 b) ----
    uint32_t sd[2][2], sm_[2][2];
    {
        uint32_t hb0 = smem_u32(&hbuf[0][0][0]);
        uint32_t off = (uint32_t)(((l & 1) * HID + u0 + u) * 4);
#pragma unroll
        for (int buf = 0; buf < 2; ++buf) {
            uint32_t laddr = hb0 + (uint32_t)(buf * 2 * HID * 4) + off;
            sd[buf][0] = mapa_u32(laddr, (uint32_t)g);
            sd[buf][1] = mapa_u32(laddr, (uint32_t)g + 4);
            sm_[buf][0] = mapa_u32(mbar_u32[buf], (uint32_t)g);
            sm_[buf][1] = mapa_u32(mbar_u32[buf], (uint32_t)g + 4);
        }
    }

    const float* zp = g_zx + (size_t)(b0 + kh) * G4 + row;  // zx(g, b=kh, u)
    float c_reg = 0.f;     // cell state: lane l==0 holds b0, l==1 holds b1

    for (int t = 0; t < S_LEN; ++t) {
        const bool last = (t == S_LEN - 1);

        // prefetch zx (issued before the wait; DRAM latency hides under it)
        float zxv = __ldcs(zp);
        zp += (size_t)BATCH * G4;

        // arm this step's inbound barrier (tx-before-expect is commutative)
        if (tid == 6 && !last)
            mbar_expect_tx(mbar_u32[t & 1], TX_BYTES);

        ull a0 = 0ull, a1 = 0ull, a2 = 0ull, a3 = 0ull;
        if (t > 0) {
            mbar_wait(mbar_u32[(t - 1) & 1], ((t - 1) >> 1) & 1);
            const int buf = (t - 1) & 1;
            const ulonglong2* h0 = reinterpret_cast<const ulonglong2*>(&hbuf[buf][0][0]);
            const ulonglong2* h1 = reinterpret_cast<const ulonglong2*>(&hbuf[buf][1][0]);
#pragma unroll
            for (int j = 0; j < 32; ++j) {
                const int G = 2 * j + kh;
                ulonglong2 p = h0[G];
                FMA2(a0, Wr[2 * j],     p.x);
                FMA2(a1, Wr[2 * j + 1], p.y);
                ulonglong2 q = h1[G];
                FMA2(a2, Wr[2 * j],     q.x);
                FMA2(a3, Wr[2 * j + 1], q.y);
            }
        }
        float v0 = hsum2(a0) + hsum2(a1);    // partial z[g][b0] over my k-half
        float v1 = hsum2(a2) + hsum2(a3);    // partial z[g][b1]
        if (kh == 0) v0 += zxv; else v1 += zxv;   // zx(g,b) added exactly once

        // reduce over kh (lanes differing in bit0)
        v0 += __shfl_xor_sync(0xffffffffu, v0, 1);
        v1 += __shfl_xor_sync(0xffffffffu, v1, 1);

        // gather all 4 gates (sources: lane 2*gg within the 8-lane group)
        float zb0[4], zb1[4];
#pragma unroll
        for (int gg = 0; gg < 4; ++gg) {
            zb0[gg] = __shfl_sync(0xffffffffu, v0, 2 * gg, 8);
            zb1[gg] = __shfl_sync(0xffffffffu, v1, 2 * gg, 8);
        }

        float h = 0.f;
        if (l < 2) {   // lane 0 -> batch b0, lane 1 -> batch b1
            float zi = l ? zb1[0] : zb0[0];
            float zf = l ? zb1[1] : zb0[1];
            float zg_ = l ? zb1[2] : zb0[2];
            float zo = l ? zb1[3] : zb0[3];
            float c = sigf(zf) * c_reg + sigf(zi) * tanh_f(zg_);
            h = sigf(zo) * tanh_f(c);
            c_reg = c;

            const int gb = b0 + l, gu = u0 + u;
            __stcs(&out[((size_t)gb * S_LEN + t) * HID + gu], h);
            if (last) {
                size_t tail = (size_t)BATCH * S_LEN * HID;
                out[tail + gb * HID + gu] = h;                 // final h
                out[tail + BATCH * HID + gb * HID + gu] = c;   // final c
            }
        }

        if (!last) {
            // broadcast h within the group, then every lane fires 2 sends
            float h0b = __shfl_sync(0xffffffffu, h, 0, 8);
            float h1b = __shfl_sync(0xffffffffu, h, 1, 8);
            float hv = (l & 1) ? h1b : h0b;
            const int buf = t & 1;
            st_async_f32(sd[buf][0], sm_[buf][0], hv);
            st_async_f32(sd[buf][1], sm_[buf][1], hv);
        }
        // no CTA barrier needed: the mbar tx-count (all 64 values, each sent
        // after its group's dot reads) provides WAR ordering cluster-wide
    }

    // no CTA may exit while a peer's in-flight st.async could target its SMEM
    asm volatile("barrier.cluster.arrive.aligned;" ::: "memory");
    asm volatile("barrier.cluster.wait.aligned;"   ::: "memory");
}

// ---------------------------------------------------------------------------
extern "C" void kernel_launch(void* const* d_in, const int* in_sizes, int n_in,
                              void* d_out, int out_size) {
    const float* x    = (const float*)d_in[0];
    const float* emb  = (const float*)d_in[1];
    const float* W_ih = (const float*)d_in[2];
    const float* W_hh = (const float*)d_in[3];
    const float* bias = (const float*)d_in[4];
    float* out = (float*)d_out;

    zx_kernel<<<dim3(16, S_LEN), 256>>>(x, emb, W_ih, bias);
    lstm_kernel<<<NGRP * CSIZE, 256>>>(W_hh, out);
}

// round 11
// speedup vs baseline: 1.0502x; 1.0502x over previous
#include <cuda_runtime.h>
#include <cuda_bf16.h>
#include <cstddef>
#include <cstdint>

#define S_LEN   2048
#define BATCH   32
#define IN_DIM  64
#define EMB_DIM 32
#define HID     256
#define XE      96
#define G4      1024
#define NGRP    16      // batch groups = clusters
#define CSIZE   8       // CTAs per cluster
#define NT      512     // threads per recurrent CTA
#define TX_BYTES 2048   // per-step tx into each CTA's mbar: 8 src * 64 floats * 4B

typedef unsigned long long ull;

// ---- device scratch (module global: the sanctioned scratch mechanism) ----
__device__ float g_zx[(size_t)S_LEN * BATCH * G4];   // [t][b][row], 256 MiB

namespace {
struct EagerLoad {  // force module load before harness mem checkpoints
    EagerLoad() { void* p = nullptr; (void)cudaGetSymbolAddress(&p, g_zx); }
};
static EagerLoad eager_;
}

// ---- fast accurate activations --------------------------------------------
__device__ __forceinline__ float sigf(float x) {
    return __fdividef(1.f, 1.f + __expf(-x));
}
__device__ __forceinline__ float tanh_f(float x) {
    float ax = fabsf(x);
    float e  = __expf(-2.f * ax);            // in (0,1], never overflows
    return copysignf(__fdividef(1.f - e, 1.f + e), x);
}

// ---- f32x2 packed FMA (sm_10x; ptxas never auto-fuses this) ---------------
#define FMA2(d, a, b) \
    asm("fma.rn.f32x2 %0, %1, %2, %0;" : "+l"(d) : "l"(a), "l"(b))

__device__ __forceinline__ float hsum2(ull v) {
    float lo, hi;
    asm("mov.b64 {%0,%1}, %2;" : "=f"(lo), "=f"(hi) : "l"(v));
    return lo + hi;
}

__device__ __forceinline__ uint32_t smem_u32(const void* p) {
    uint32_t a;
    asm("{ .reg .u64 t; cvta.to.shared.u64 t, %1; cvt.u32.u64 %0, t; }"
        : "=r"(a) : "l"(p));
    return a;
}
__device__ __forceinline__ uint32_t mapa_u32(uint32_t laddr, uint32_t rank) {
    uint32_t ra;
    asm("mapa.shared::cluster.u32 %0, %1, %2;" : "=r"(ra) : "r"(laddr), "r"(rank));
    return ra;
}
// remote smem store + remote mbarrier tx-complete, hardware-ordered, async
__device__ __forceinline__ void st_async_f32(uint32_t raddr, uint32_t rmbar, float v) {
    asm volatile(
        "st.async.weak.shared::cluster.mbarrier::complete_tx::bytes.f32 [%0], %1, [%2];"
        :: "r"(raddr), "f"(v), "r"(rmbar) : "memory");
}
__device__ __forceinline__ void mbar_expect_tx(uint32_t mbar, uint32_t tx) {
    asm volatile("mbarrier.arrive.expect_tx.shared.b64 _, [%0], %1;"
                 :: "r"(mbar), "r"(tx) : "memory");
}
__device__ __forceinline__ void mbar_wait(uint32_t mbar, uint32_t parity) {
    asm volatile(
        "{\n\t.reg .pred P;\n"
        "WL_%=:\n\t"
        "mbarrier.try_wait.parity.acquire.cluster.shared::cta.b64 P, [%0], %1, 0x989680;\n\t"
        "@!P bra WL_%=;\n\t}"
        :: "r"(mbar), "r"(parity) : "memory");
}

// ---------------------------------------------------------------------------
// Kernel A: zx[t][b][row] = bias[row] + sum_i [x|emb][b][t][i] * W_ih[row][i]
// grid (16 row-tiles, 2048 t), 256 threads, FFMA2.  (known-good)
// ---------------------------------------------------------------------------
__global__ void __launch_bounds__(256) zx_kernel(
    const float* __restrict__ x, const float* __restrict__ emb,
    const float* __restrict__ W_ih, const float* __restrict__ bias)
{
    const int t = blockIdx.y, rbase = blockIdx.x * 64, tid = threadIdx.x;

    __shared__ __align__(16) float xe_s[BATCH][100];
    __shared__ __align__(16) float W_s[64][100];

    for (int idx = tid; idx < BATCH * IN_DIM; idx += 256) {
        int b = idx >> 6, i = idx & 63;
        xe_s[b][i] = x[((size_t)b * S_LEN + t) * IN_DIM + i];
    }
    for (int idx = tid; idx < BATCH * EMB_DIM; idx += 256) {
        int b = idx >> 5, i = idx & 31;
        xe_s[b][IN_DIM + i] = emb[((size_t)b * S_LEN + t) * EMB_DIM + i];
    }
    for (int idx = tid; idx < 64 * XE; idx += 256) {
        int r = idx / XE, i = idx - r * XE;
        W_s[r][i] = W_ih[(size_t)(rbase + r) * XE + i];
    }
    __syncthreads();

    const int m = tid & 15, b0 = (tid >> 4) * 2;

    ull acc[4][2][2];
#pragma unroll
    for (int j = 0; j < 4; ++j)
#pragma unroll
        for (int b = 0; b < 2; ++b)
            acc[j][b][0] = acc[j][b][1] = 0ull;

    const ulonglong2* xv0 = reinterpret_cast<const ulonglong2*>(&xe_s[b0][0]);
    const ulonglong2* xv1 = reinterpret_cast<const ulonglong2*>(&xe_s[b0 + 1][0]);
#pragma unroll
    for (int k4 = 0; k4 < XE / 4; ++k4) {
        ulonglong2 xa = xv0[k4], xb = xv1[k4];
#pragma unroll
        for (int j = 0; j < 4; ++j) {
            ulonglong2 w = reinterpret_cast<const ulonglong2*>(&W_s[m + 16 * j][0])[k4];
            FMA2(acc[j][0][0], w.x, xa.x);
            FMA2(acc[j][0][1], w.y, xa.y);
            FMA2(acc[j][1][0], w.x, xb.x);
            FMA2(acc[j][1][1], w.y, xb.y);
        }
    }
#pragma unroll
    for (int j = 0; j < 4; ++j) {
        int row = rbase + m + 16 * j;
        float bv = __ldg(&bias[row]);
        size_t base = ((size_t)t * BATCH + b0) * G4 + row;
        g_zx[base]      = hsum2(acc[j][0][0]) + hsum2(acc[j][0][1]) + bv;
        g_zx[base + G4] = hsum2(acc[j][1][0]) + hsum2(acc[j][1][1]) + bv;
    }
}

// ---------------------------------------------------------------------------
// Kernel B: persistent LSTM. 16 independent 8-CTA clusters (2 batches each),
// 512 threads/CTA. Thread (r = tid&127, kq = tid>>7): gate-row r over
// k-quarter kq (64 k = 32 f32x2 pairs, 64 regs of W), both batches.
// Reduction via part[4][2][128] smem + one __syncthreads. h exchanged via
// st.async + mbarrier tx counting; zx prefetched one step ahead.
// ---------------------------------------------------------------------------
__global__ void __launch_bounds__(NT, 1) __cluster_dims__(CSIZE, 1, 1)
lstm_kernel(const float* __restrict__ W_hh, float* __restrict__ out)
{
    __shared__ __align__(16) float hbuf[2][2][HID];       // [buf][b][k]
    __shared__ __align__(16) float part[4][2][128];       // [kq][b][r]
    __shared__ __align__(8)  ull   mbar[2];

    const int tid = threadIdx.x;
    const int grp = blockIdx.x / CSIZE;
    uint32_t rank;
    asm("mov.u32 %0, %%cluster_ctarank;" : "=r"(rank));
    const int b0 = grp * 2;
    const int u0 = (int)rank * 32;

    const uint32_t mbar_u32[2] = { smem_u32(&mbar[0]), smem_u32(&mbar[1]) };
    if (tid == 0) {
        asm volatile("mbarrier.init.shared.b64 [%0], 1;" :: "r"(mbar_u32[0]) : "memory");
        asm volatile("mbarrier.init.shared.b64 [%0], 1;" :: "r"(mbar_u32[1]) : "memory");
    }
    __syncthreads();
    // all mbarriers must be initialized before any peer's st.async can land
    asm volatile("barrier.cluster.arrive.aligned;" ::: "memory");
    asm volatile("barrier.cluster.wait.aligned;"   ::: "memory");

    const int r   = tid & 127;        // row: gate g=r>>5, unit uu=r&31
    const int kq  = tid >> 7;         // k-quarter 0..3
    const int g   = r >> 5, uu = r & 31;
    const int row = g * HID + u0 + uu;

    // ---- W slice in registers: pairs [kq*32, kq*32+32) = 64 regs ----
    ull Wr[32];
    {
        const ulonglong2* wrow = reinterpret_cast<const ulonglong2*>(
            W_hh + (size_t)row * HID + kq * 64);
#pragma unroll
        for (int i = 0; i < 16; ++i) {
            ulonglong2 v = __ldg(&wrow[i]);
            Wr[2 * i]     = v.x;
            Wr[2 * i + 1] = v.y;
        }
    }

    // gate-thread constants (tid < 64): b = tid>>5, u = tid&31
    const int gb = b0 + (tid >> 5);
    const int gu = u0 + (tid & 31);
    const uint32_t hoff_b = (uint32_t)(((tid >> 5) * HID + gu) * 4);
    const uint32_t hb_base[2] = { smem_u32(&hbuf[0][0][0]), smem_u32(&hbuf[1][0][0]) };
    float c_reg = 0.f;

    const float* zx_base = g_zx + (size_t)b0 * G4 + row;   // kq==0 threads only

    // zx pipeline: znext holds step-t values at top of iteration t
    float zna = 0.f, znb = 0.f;
    if (kq == 0) {
        zna = __ldcs(zx_base);
        znb = __ldcs(zx_base + G4);
    }

    for (int t = 0; t < S_LEN; ++t) {
        const bool last = (t == S_LEN - 1);
        const float zxa = zna, zxb = znb;

        // arm this step's inbound barrier (tx-before-expect is commutative)
        if (tid == NT - 1 && !last)
            mbar_expect_tx(mbar_u32[t & 1], TX_BYTES);

        ull a0 = 0ull, a1 = 0ull, a2 = 0ull, a3 = 0ull;
        if (t > 0) {
            mbar_wait(mbar_u32[(t - 1) & 1], ((t - 1) >> 1) & 1);

            // prefetch NEXT step's zx right after the wait: its DRAM latency
            // hides under this whole step (dot+gates+exchange)
            if (kq == 0 && !last) {
                const float* zp = zx_base + (size_t)(t + 1) * (BATCH * G4);
                zna = __ldcs(zp);
                znb = __ldcs(zp + G4);
            }

            const int buf = (t - 1) & 1;
            const ulonglong2* h0 = reinterpret_cast<const ulonglong2*>(
                &hbuf[buf][0][kq * 64]);
            const ulonglong2* h1 = reinterpret_cast<const ulonglong2*>(
                &hbuf[buf][1][kq * 64]);
#pragma unroll
            for (int i = 0; i < 16; ++i) {
                ulonglong2 p = h0[i];
                FMA2(a0, Wr[2 * i],     p.x);
                FMA2(a1, Wr[2 * i + 1], p.y);
                ulonglong2 q = h1[i];
                FMA2(a2, Wr[2 * i],     q.x);
                FMA2(a3, Wr[2 * i + 1], q.y);
            }
        } else if (kq == 0) {
            const float* zp = zx_base + (size_t)(BATCH * G4);
            zna = __ldcs(zp);
            znb = __ldcs(zp + G4);
        }
        float pb0 = hsum2(a0) + hsum2(a1);
        float pb1 = hsum2(a2) + hsum2(a3);
        if (kq == 0) { pb0 += zxa; pb1 += zxb; }
        part[kq][0][r] = pb0;
        part[kq][1][r] = pb1;
        // Single per-step CTA barrier; also provides WAR ordering: the scatter
        // below follows every thread's dot reads of hbuf[(t-1)&1].
        __syncthreads();

        if (tid < 64) {
            const int b = tid >> 5, u = tid & 31;
            float z4[4];
#pragma unroll
            for (int gg = 0; gg < 4; ++gg)
                z4[gg] = ((part[0][b][gg * 32 + u]  + part[1][b][gg * 32 + u]) +
                          (part[2][b][gg * 32 + u]  + part[3][b][gg * 32 + u]));
            float c = sigf(z4[1]) * c_reg + sigf(z4[0]) * tanh_f(z4[2]);
            float h = sigf(z4[3]) * tanh_f(c);
            c_reg = c;

            __stcs(&out[((size_t)gb * S_LEN + t) * HID + gu], h);
            if (last) {
                size_t tail = (size_t)BATCH * S_LEN * HID;
                out[tail + gb * HID + gu] = h;                 // final h
                out[tail + BATCH * HID + gb * HID + gu] = c;   // final c
            } else {
                // async scatter h(t) to hbuf[t&1] in every CTA; each store
                // carries 4B of tx-credit to that CTA's mbar[t&1]
                uint32_t laddr = hb_base[t & 1] + hoff_b;
                uint32_t lmbar = mbar_u32[t & 1];
#pragma unroll
                for (uint32_t pr = 0; pr < CSIZE; ++pr)
                    st_async_f32(mapa_u32(laddr, pr), mapa_u32(lmbar, pr), h);
            }
        }
        // no trailing barrier: next step's mbar wait is the synchronization
    }

    // no CTA may exit while a peer's in-flight st.async could target its SMEM
    asm volatile("barrier.cluster.arrive.aligned;" ::: "memory");
    asm volatile("barrier.cluster.wait.aligned;"   ::: "memory");
}

// ---------------------------------------------------------------------------
extern "C" void kernel_launch(void* const* d_in, const int* in_sizes, int n_in,
                              void* d_out, int out_size) {
    const float* x    = (const float*)d_in[0];
    const float* emb  = (const float*)d_in[1];
    const float* W_ih = (const float*)d_in[2];
    const float* W_hh = (const float*)d_in[3];
    const float* bias = (const float*)d_in[4];
    float* out = (float*)d_out;

    zx_kernel<<<dim3(16, S_LEN), 256>>>(x, emb, W_ih, bias);
    lstm_kernel<<<NGRP * CSIZE, NT>>>(W_hh, out);
}